// round 7
// baseline (speedup 1.0000x reference)
#include <cuda_runtime.h>
#include <cuda_bf16.h>
#include <float.h>
#include <math.h>

// Problem constants (from reference)
#define H 512
#define W 512
#define PSIZE 4
#define NEUR 32
#define TOPK 4
#define S2 16
#define NH 509            // (512 - 3) / 1
#define NW 509
#define NZ (NH * NW)      // 259081
#define EPSV 1e-8f
// near-tie window: >> fast-vs-exact pre delta (~1e-6), << typical 4th/5th
// gap (~1e-2) -> exact path runs on only a few % of rows
#define TIE_TAU 5e-4f

// One warp per patch z; lane n = neuron n.
//
// Two-tier numerics:
//   FAST (every warp): FMA dot + norms + one fast division. Cheap (~150
//     warp-issues). Values differ from the reference by ~1e-7 rel -- far
//     below the error budget. Top-4 runs on these values.
//   EXACT (warps with any lane within TIE_TAU of the fast threshold):
//     bit-exact emulation of XLA's lowering (rounded mul -> rounded add, no
//     FMA; per-element rounded divide BEFORE the dot; sequential ascending
//     reductions). The selection -- the only thing that can move rel_err --
//     is decided by this path exactly as in the R6 passing kernel.
__global__ __launch_bounds__(256)
void topk_layer2d_kernel(const float* __restrict__ x,
                         const float* __restrict__ Wz,
                         float* __restrict__ out)
{
    const int lane = threadIdx.x & 31;
    const int z    = blockIdx.x * (blockDim.x >> 5) + (threadIdx.x >> 5);
    if (z >= NZ) return;

    const int r = z / NW;
    const int c = z - r * NW;

    // ---- weight row: 4 independent float4 loads (front-batched, MLP=4) ----
    const float4* wp = reinterpret_cast<const float4*>(
        Wz + ((size_t)z * NEUR + (size_t)lane) * S2);
    const float4 w0 = wp[0];
    const float4 w1 = wp[1];
    const float4 w2 = wp[2];
    const float4 w3 = wp[3];

    float w[S2];
    w[0]=w0.x;  w[1]=w0.y;  w[2]=w0.z;  w[3]=w0.w;
    w[4]=w1.x;  w[5]=w1.y;  w[6]=w1.z;  w[7]=w1.w;
    w[8]=w2.x;  w[9]=w2.y;  w[10]=w2.z; w[11]=w2.w;
    w[12]=w3.x; w[13]=w3.y; w[14]=w3.z; w[15]=w3.w;

    // ---- patch (uniform-address broadcast loads, L1-resident) ----
    float p[S2];
#pragma unroll
    for (int a = 0; a < PSIZE; a++)
#pragma unroll
        for (int b = 0; b < PSIZE; b++)
            p[a * PSIZE + b] = __ldg(&x[(r + a) * W + (c + b)]);

    const unsigned FULL = 0xFFFFFFFFu;

    // ================= FAST PATH =================
    float pacc = 0.f, wacc = 0.f, dp = 0.f;
#pragma unroll
    for (int d = 0; d < S2; d++) {
        pacc = fmaf(p[d], p[d], pacc);
        wacc = fmaf(w[d], w[d], wacc);
        dp   = fmaf(w[d], p[d], dp);
    }
    const float den  = (sqrtf(wacc) + EPSV) * (sqrtf(pacc) + EPSV);
    float pre  = __fdividef(dp, den);

    // top-4 threshold: 4 rounds of warp max-reduce + retire one max lane
    float thr = -FLT_MAX;
    {
        bool alive = true;
#pragma unroll
        for (int k = 0; k < TOPK; k++) {
            float m = alive ? pre : -FLT_MAX;
#pragma unroll
            for (int off = 16; off > 0; off >>= 1)
                m = fmaxf(m, __shfl_xor_sync(FULL, m, off));
            thr = m;
            unsigned ball = __ballot_sync(FULL, alive && (pre == m));
            if (lane == (int)__ffs(ball) - 1) alive = false;
        }
    }

    // ================= EXACT RESCUE (rare, warp-uniform) =================
    const bool risky = fabsf(pre - thr) < TIE_TAU;
    if (__ballot_sync(FULL, risky)) {
        // patch norm: rounded square + sequential rounded adds, ascending
        float pa = 0.f;
#pragma unroll
        for (int d = 0; d < S2; d++)
            pa = __fadd_rn(pa, __fmul_rn(p[d], p[d]));
        const float pden = __fadd_rn(__fsqrt_rn(pa), EPSV);
        // pn is warp-uniform: lane d (<16) does element d's rounded divide
        const float pn_mine = (lane < S2) ? __fdiv_rn(p[lane], pden) : 0.f;

        float wa = 0.f;
#pragma unroll
        for (int d = 0; d < S2; d++)
            wa = __fadd_rn(wa, __fmul_rn(w[d], w[d]));
        const float wden = __fadd_rn(__fsqrt_rn(wa), EPSV);

        // pre = reduce(mul): rounded mul, rounded add, ascending (no FMA)
        float acc = 0.f;
#pragma unroll
        for (int d = 0; d < S2; d++) {
            const float pn_d = __shfl_sync(FULL, pn_mine, d);
            const float wn_d = __fdiv_rn(w[d], wden);
            acc = __fadd_rn(acc, __fmul_rn(wn_d, pn_d));
        }
        pre = acc;   // exact values for this row (matches R6 bit-for-bit)

        thr = -FLT_MAX;
        bool alive = true;
#pragma unroll
        for (int k = 0; k < TOPK; k++) {
            float m = alive ? pre : -FLT_MAX;
#pragma unroll
            for (int off = 16; off > 0; off >>= 1)
                m = fmaxf(m, __shfl_xor_sync(FULL, m, off));
            thr = m;
            unsigned ball = __ballot_sync(FULL, alive && (pre == m));
            if (lane == (int)__ffs(ball) - 1) alive = false;
        }
    }

    // coalesced 128B store per warp
    out[(size_t)z * NEUR + lane] = (pre >= thr) ? pre : 0.f;
}

extern "C" void kernel_launch(void* const* d_in, const int* in_sizes, int n_in,
                              void* d_out, int out_size)
{
    const float* x  = (const float*)d_in[0];   // (512, 512) fp32
    const float* Wz = (const float*)d_in[1];   // (NZ, 32, 16) fp32
    float* out = (float*)d_out;                // (NZ, 32) fp32

    const int WARPS_PER_BLOCK = 8;             // 256 threads
    const int blocks = (NZ + WARPS_PER_BLOCK - 1) / WARPS_PER_BLOCK;
    topk_layer2d_kernel<<<blocks, WARPS_PER_BLOCK * 32>>>(x, Wz, out);
}

// round 8
// speedup vs baseline: 1.3436x; 1.3436x over previous
#include <cuda_runtime.h>
#include <cuda_bf16.h>
#include <float.h>
#include <math.h>

// Problem constants (from reference)
#define H 512
#define W 512
#define PSIZE 4
#define NEUR 32
#define TOPK 4
#define S2 16
#define NH 509            // (512 - 3) / 1
#define NW 509
#define NZ (NH * NW)      // 259081
#define EPSV 1e-8f
// near-tie window: >> fast-vs-exact pre delta (~1e-6), << typical 4th/5th
// gap (~6e-3) -> exact path runs on ~8% of rows
#define TIE_TAU 5e-4f

// One warp per patch z; lane n = neuron n.
//
// Two-tier numerics:
//   FAST (every warp): FMA dot + norms + one fast division (~150 warp
//     issues). Values are within ~1e-6 of the reference -- negligible for
//     rel_err. Top-4 runs on these values.
//   EXACT (only warps where >4 lanes lie within TIE_TAU of the fast
//     threshold, i.e. the 4th/5th gap is < TIE_TAU): bit-exact emulation of
//     XLA's lowering (rounded mul -> rounded add, no FMA; per-element
//     rounded divide BEFORE the dot; ascending reductions), deciding the
//     selection exactly as the R6 passing kernel did.
//   NOTE the risky test counts candidates ABOVE thr-tau; testing
//   |pre-thr|<tau is always true for the threshold lane itself (R7 bug:
//   rescue ran on 100% of warps).
__global__ __launch_bounds__(256)
void topk_layer2d_kernel(const float* __restrict__ x,
                         const float* __restrict__ Wz,
                         float* __restrict__ out)
{
    const int lane = threadIdx.x & 31;
    const int z    = blockIdx.x * (blockDim.x >> 5) + (threadIdx.x >> 5);
    if (z >= NZ) return;

    const int r = z / NW;
    const int c = z - r * NW;

    // ---- weight row: 4 independent float4 loads (front-batched, MLP=4) ----
    const float4* wp = reinterpret_cast<const float4*>(
        Wz + ((size_t)z * NEUR + (size_t)lane) * S2);
    const float4 w0 = wp[0];
    const float4 w1 = wp[1];
    const float4 w2 = wp[2];
    const float4 w3 = wp[3];

    float w[S2];
    w[0]=w0.x;  w[1]=w0.y;  w[2]=w0.z;  w[3]=w0.w;
    w[4]=w1.x;  w[5]=w1.y;  w[6]=w1.z;  w[7]=w1.w;
    w[8]=w2.x;  w[9]=w2.y;  w[10]=w2.z; w[11]=w2.w;
    w[12]=w3.x; w[13]=w3.y; w[14]=w3.z; w[15]=w3.w;

    // ---- patch (uniform-address broadcast loads, L1-resident) ----
    float p[S2];
#pragma unroll
    for (int a = 0; a < PSIZE; a++)
#pragma unroll
        for (int b = 0; b < PSIZE; b++)
            p[a * PSIZE + b] = __ldg(&x[(r + a) * W + (c + b)]);

    const unsigned FULL = 0xFFFFFFFFu;

    // ================= FAST PATH =================
    float pacc = 0.f, wacc = 0.f, dp = 0.f;
#pragma unroll
    for (int d = 0; d < S2; d++) {
        pacc = fmaf(p[d], p[d], pacc);
        wacc = fmaf(w[d], w[d], wacc);
        dp   = fmaf(w[d], p[d], dp);
    }
    const float den = (sqrtf(wacc) + EPSV) * (sqrtf(pacc) + EPSV);
    float pre = __fdividef(dp, den);

    // top-4 threshold: 4 rounds of warp max-reduce + retire one max lane
    float thr = -FLT_MAX;
    {
        bool alive = true;
#pragma unroll
        for (int k = 0; k < TOPK; k++) {
            float m = alive ? pre : -FLT_MAX;
#pragma unroll
            for (int off = 16; off > 0; off >>= 1)
                m = fmaxf(m, __shfl_xor_sync(FULL, m, off));
            thr = m;
            unsigned ball = __ballot_sync(FULL, alive && (pre == m));
            if (lane == (int)__ffs(ball) - 1) alive = false;
        }
    }

    // ================= EXACT RESCUE (rare, warp-uniform) =================
    // Risky iff MORE than 4 lanes are candidates at thr - tau: then the
    // 4th/5th gap is below tau and the fast ordering might disagree with
    // the exact one. Exactly 4 candidates -> gap > tau -> provably safe.
    const unsigned nearMask = __ballot_sync(FULL, pre >= thr - TIE_TAU);
    if (__popc(nearMask) > 4) {
        // patch norm: rounded square + sequential rounded adds, ascending
        float pa = 0.f;
#pragma unroll
        for (int d = 0; d < S2; d++)
            pa = __fadd_rn(pa, __fmul_rn(p[d], p[d]));
        const float pden = __fadd_rn(__fsqrt_rn(pa), EPSV);
        // pn is warp-uniform: lane d (<16) does element d's rounded divide
        const float pn_mine = (lane < S2) ? __fdiv_rn(p[lane], pden) : 0.f;

        float wa = 0.f;
#pragma unroll
        for (int d = 0; d < S2; d++)
            wa = __fadd_rn(wa, __fmul_rn(w[d], w[d]));
        const float wden = __fadd_rn(__fsqrt_rn(wa), EPSV);

        // pre = reduce(mul): rounded mul, rounded add, ascending (no FMA)
        float acc = 0.f;
#pragma unroll
        for (int d = 0; d < S2; d++) {
            const float pn_d = __shfl_sync(FULL, pn_mine, d);
            const float wn_d = __fdiv_rn(w[d], wden);
            acc = __fadd_rn(acc, __fmul_rn(wn_d, pn_d));
        }
        pre = acc;   // exact values for this row (matches R6 bit-for-bit)

        thr = -FLT_MAX;
        bool alive = true;
#pragma unroll
        for (int k = 0; k < TOPK; k++) {
            float m = alive ? pre : -FLT_MAX;
#pragma unroll
            for (int off = 16; off > 0; off >>= 1)
                m = fmaxf(m, __shfl_xor_sync(FULL, m, off));
            thr = m;
            unsigned ball = __ballot_sync(FULL, alive && (pre == m));
            if (lane == (int)__ffs(ball) - 1) alive = false;
        }
    }

    // coalesced 128B store per warp
    out[(size_t)z * NEUR + lane] = (pre >= thr) ? pre : 0.f;
}

extern "C" void kernel_launch(void* const* d_in, const int* in_sizes, int n_in,
                              void* d_out, int out_size)
{
    const float* x  = (const float*)d_in[0];   // (512, 512) fp32
    const float* Wz = (const float*)d_in[1];   // (NZ, 32, 16) fp32
    float* out = (float*)d_out;                // (NZ, 32) fp32

    const int WARPS_PER_BLOCK = 8;             // 256 threads
    const int blocks = (NZ + WARPS_PER_BLOCK - 1) / WARPS_PER_BLOCK;
    topk_layer2d_kernel<<<blocks, WARPS_PER_BLOCK * 32>>>(x, Wz, out);
}